// round 2
// baseline (speedup 1.0000x reference)
#include <cuda_runtime.h>
#include <cuda_bf16.h>

// ---------------------------------------------------------------------------
// Problem constants (fixed shapes from reference):
//   x:      [32, 256, 56, 56] f32
//   weight: [256, 256, 3, 3]  f32
//   gamma/beta/mean/var: [256], alpha: [1]
//   out:    [32, 256, 56, 56] f32
// ---------------------------------------------------------------------------

#define B_     32
#define CIN_   256
#define COUT_  256
#define HW_    56
#define WN_    (COUT_ * CIN_ * 9)   // 589824 weights
#define BN_EPS 1e-5f

// Scratch: quantized weights (allocation-free via __device__ global)
__device__ float g_wq[WN_];
__device__ int   g_maxbits;

// ---------------------------------------------------------------------------
// Kernel 1: reset reduction scalar
// ---------------------------------------------------------------------------
__global__ void init_max_kernel() { g_maxbits = 0; }

// ---------------------------------------------------------------------------
// Kernel 2: max|w| reduction (tanh is monotone: max|tanh(w)| = tanh(max|w|))
// ---------------------------------------------------------------------------
__global__ void wmax_kernel(const float* __restrict__ w) {
    float m = 0.0f;
    for (int i = blockIdx.x * blockDim.x + threadIdx.x; i < WN_;
         i += gridDim.x * blockDim.x)
        m = fmaxf(m, fabsf(w[i]));
    #pragma unroll
    for (int o = 16; o > 0; o >>= 1)
        m = fmaxf(m, __shfl_xor_sync(0xFFFFFFFFu, m, o));
    if ((threadIdx.x & 31) == 0)
        atomicMax(&g_maxbits, __float_as_int(m));  // all values >= 0: int compare ok
}

// ---------------------------------------------------------------------------
// Kernel 3: DoReFa weight quantization
//   t = tanh(w); u = t/(2*T) + 0.5; q = rint(u*15)/15; wq = 2q - 1
// ---------------------------------------------------------------------------
__global__ void wquant_kernel(const float* __restrict__ w) {
    int i = blockIdx.x * blockDim.x + threadIdx.x;
    if (i >= WN_) return;
    float T = tanhf(__int_as_float(g_maxbits));
    float t = tanhf(w[i]);
    float u = t / (2.0f * T) + 0.5f;
    float q = rintf(u * 15.0f) * (1.0f / 15.0f);
    g_wq[i] = 2.0f * q - 1.0f;
}

// ---------------------------------------------------------------------------
// Kernel 4: fused 3x3 conv (pad 1) + BN (running stats) + PACT 4-bit quant
//
// Block: one image n, 64 c_out, 8x8 spatial tile. 256 threads.
// Thread: 4 c_out x 2x2 pixels (16 accumulators).
//   tid = co_group(4b hi) | quad(4b lo); quad = 4x4 grid of 2x2 pixel quads.
// Smem staging per c_in chunk of 8: input halo tile [8][10][12] (padded
// stride -> conflict-free even-bank reads), weights [64][8][9] (broadcast
// across 16-lane half-warps).
// ---------------------------------------------------------------------------
__global__ __launch_bounds__(256)
void conv_bn_pact_kernel(const float* __restrict__ x,
                         const float* __restrict__ gamma,
                         const float* __restrict__ beta,
                         const float* __restrict__ rmean,
                         const float* __restrict__ rvar,
                         const float* __restrict__ alpha,
                         float* __restrict__ out) {
    const int tid     = threadIdx.x;
    const int tileid  = blockIdx.x;          // 0..48
    const int ty      = tileid / 7;
    const int tx      = tileid - ty * 7;
    const int co_tile = blockIdx.y;          // 0..3 (x64 c_out)
    const int n       = blockIdx.z;          // 0..31

    const int qid = tid & 15;
    const int cog = tid >> 4;                // 0..15 (x4 c_out)
    const int qy  = qid >> 2;
    const int qx  = qid & 3;
    const int co_base = cog * 4;

    __shared__ float s_in[8][10][12];
    __shared__ float s_w[64][8][9];

    float acc[4][2][2] = {};

    const int y0 = ty * 8, x0 = tx * 8;

    for (int cin0 = 0; cin0 < CIN_; cin0 += 8) {
        // --- stage input halo tile: 8 channels x 10x10 ---
        for (int i = tid; i < 800; i += 256) {
            int ci  = i / 100;
            int rem = i - ci * 100;
            int r   = rem / 10;
            int c   = rem - r * 10;
            int iy  = y0 + r - 1;
            int ix  = x0 + c - 1;
            float v = 0.0f;
            if (iy >= 0 && iy < HW_ && ix >= 0 && ix < HW_)
                v = x[(((n * CIN_) + cin0 + ci) * HW_ + iy) * HW_ + ix];
            s_in[ci][r][c] = v;
        }
        // --- stage quantized weights: 64 c_out x 8 c_in x 9 ---
        for (int i = tid; i < 4608; i += 256) {
            int co  = i / 72;
            int rem = i - co * 72;
            int ci  = rem / 9;
            int k   = rem - ci * 9;
            s_w[co][ci][k] =
                g_wq[((co_tile * 64 + co) * CIN_ + cin0 + ci) * 9 + k];
        }
        __syncthreads();

        #pragma unroll
        for (int ci = 0; ci < 8; ++ci) {
            float xin[4][4];
            #pragma unroll
            for (int r = 0; r < 4; ++r)
                #pragma unroll
                for (int c = 0; c < 4; ++c)
                    xin[r][c] = s_in[ci][2 * qy + r][2 * qx + c];

            #pragma unroll
            for (int i = 0; i < 4; ++i) {
                float w[9];
                #pragma unroll
                for (int k = 0; k < 9; ++k)
                    w[k] = s_w[co_base + i][ci][k];
                #pragma unroll
                for (int dy = 0; dy < 2; ++dy)
                    #pragma unroll
                    for (int dx = 0; dx < 2; ++dx) {
                        float s = acc[i][dy][dx];
                        #pragma unroll
                        for (int ky = 0; ky < 3; ++ky)
                            #pragma unroll
                            for (int kx = 0; kx < 3; ++kx)
                                s = fmaf(w[ky * 3 + kx],
                                         xin[dy + ky][dx + kx], s);
                        acc[i][dy][dx] = s;
                    }
            }
        }
        __syncthreads();
    }

    // --- epilogue: BN + PACT ---
    const float a = __ldg(alpha);
    #pragma unroll
    for (int i = 0; i < 4; ++i) {
        const int co_g = co_tile * 64 + co_base + i;
        const float inv = gamma[co_g] / sqrtf(rvar[co_g] + BN_EPS);
        const float b   = beta[co_g] - rmean[co_g] * inv;
        #pragma unroll
        for (int dy = 0; dy < 2; ++dy)
            #pragma unroll
            for (int dx = 0; dx < 2; ++dx) {
                const int oy = y0 + 2 * qy + dy;
                const int ox = x0 + 2 * qx + dx;
                float v = acc[i][dy][dx] * inv + b;
                v = fminf(fmaxf(v, 0.0f), a);
                v = rintf(v * 15.0f / a) * (a / 15.0f);
                out[((n * COUT_ + co_g) * HW_ + oy) * HW_ + ox] = v;
            }
    }
}

// ---------------------------------------------------------------------------
// Launch
// ---------------------------------------------------------------------------
extern "C" void kernel_launch(void* const* d_in, const int* in_sizes, int n_in,
                              void* d_out, int out_size) {
    const float* x      = (const float*)d_in[0];
    const float* weight = (const float*)d_in[1];
    const float* gamma  = (const float*)d_in[2];
    const float* beta   = (const float*)d_in[3];
    const float* rmean  = (const float*)d_in[4];
    const float* rvar   = (const float*)d_in[5];
    const float* alpha  = (const float*)d_in[6];
    float* out = (float*)d_out;

    init_max_kernel<<<1, 1>>>();
    wmax_kernel<<<576, 256>>>(weight);
    wquant_kernel<<<(WN_ + 255) / 256, 256>>>(weight);

    dim3 grid(49, 4, B_);
    conv_bn_pact_kernel<<<grid, 256>>>(x, gamma, beta, rmean, rvar, alpha, out);
}

// round 4
// speedup vs baseline: 1.1908x; 1.1908x over previous
#include <cuda_runtime.h>
#include <cuda_fp16.h>
#include <cstdint>

// ---------------------------------------------------------------------------
// Shapes: x [32,256,56,56] f32, w [256,256,3,3] f32, out [32,256,56,56] f32
// ---------------------------------------------------------------------------
#define B_     32
#define CIN_   256
#define COUT_  256
#define HW_    56
#define WN_    (COUT_ * CIN_ * 9)
#define BN_EPS 1e-5f

// Scratch (allocation-free __device__ globals)
__device__ int    g_maxbits;
__device__ __half g_wqh[9 * COUT_ * CIN_];   // [tap][co][ci], s = 15*wq (odd ints, exact fp16)
__device__ float  g_scale[COUT_];            // gamma/sqrt(var+eps)/15
__device__ float  g_bias[COUT_];             // beta - mean*inv

// ---------------------------------------------------------------------------
// Prep kernels
// ---------------------------------------------------------------------------
__global__ void init_max_kernel() { g_maxbits = 0; }

__global__ void wmax_kernel(const float* __restrict__ w) {
    float m = 0.0f;
    for (int i = blockIdx.x * blockDim.x + threadIdx.x; i < WN_;
         i += gridDim.x * blockDim.x)
        m = fmaxf(m, fabsf(w[i]));
    #pragma unroll
    for (int o = 16; o > 0; o >>= 1)
        m = fmaxf(m, __shfl_xor_sync(0xFFFFFFFFu, m, o));
    if ((threadIdx.x & 31) == 0)
        atomicMax(&g_maxbits, __float_as_int(m));  // nonneg floats: int order ok
}

// s = 15*wq = 2*rint(u*15) - 15  (odd integer in [-15,15], exact in fp16)
__global__ void wquant_h_kernel(const float* __restrict__ w) {
    int i = blockIdx.x * blockDim.x + threadIdx.x;
    if (i >= WN_) return;
    float T = tanhf(__int_as_float(g_maxbits));
    float t = tanhf(w[i]);
    float u = t / (2.0f * T) + 0.5f;
    float s = 2.0f * rintf(u * 15.0f) - 15.0f;
    int tap = i % 9;
    int ci  = (i / 9) % CIN_;
    int co  = i / (9 * CIN_);
    g_wqh[(tap * COUT_ + co) * CIN_ + ci] = __float2half_rn(s);
}

__global__ void bnprep_kernel(const float* __restrict__ gamma,
                              const float* __restrict__ beta,
                              const float* __restrict__ mean,
                              const float* __restrict__ var) {
    int c = threadIdx.x;
    float inv = gamma[c] * rsqrtf(var[c] + BN_EPS);
    g_scale[c] = inv * (1.0f / 15.0f);   // conv accumulated 15x
    g_bias[c]  = beta[c] - mean[c] * inv;
}

// ---------------------------------------------------------------------------
// Warp-MMA primitives (sm_80+: legal on plain sm_103)
// ---------------------------------------------------------------------------
#define LDSM4(r, addr)                                                        \
    asm volatile("ldmatrix.sync.aligned.m8n8.x4.shared.b16 {%0,%1,%2,%3}, [%4];" \
        : "=r"((r)[0]), "=r"((r)[1]), "=r"((r)[2]), "=r"((r)[3]) : "r"(addr))

#define MMA16816(d, a, b0, b1)                                                \
    asm volatile("mma.sync.aligned.m16n8k16.row.col.f32.f16.f16.f32 "         \
        "{%0,%1,%2,%3}, {%4,%5,%6,%7}, {%8,%9}, {%0,%1,%2,%3};"               \
        : "+f"((d)[0]), "+f"((d)[1]), "+f"((d)[2]), "+f"((d)[3])              \
        : "r"((a)[0]), "r"((a)[1]), "r"((a)[2]), "r"((a)[3]), "r"(b0), "r"(b1))

static __device__ __forceinline__ void cp16(uint32_t dst, const void* src) {
    asm volatile("cp.async.cg.shared.global [%0], [%1], 16;"
                 :: "r"(dst), "l"(src));
}
#define CP_COMMIT() asm volatile("cp.async.commit_group;")
#define CP_WAIT0()  asm volatile("cp.async.wait_group 0;" ::: "memory")

// ---------------------------------------------------------------------------
// SMEM layout (bytes). X tiles: [6 rows][58 cols][40 ci-pad] fp16 (hi, lo).
// Pad 40 (80B stride) -> conflict-free ldmatrix + 16B-aligned cp.async rows.
// ---------------------------------------------------------------------------
#define RSTG   6
#define CSTG   58
#define CIPAD  40
#define XARR   (RSTG * CSTG * CIPAD * 2)    // 27840 per array
#define BOFF   (2 * XARR)                   // 55680
#define BBUF   (128 * CIPAD * 2)            // 10240 per buffer
#define BNOFF  (BOFF + 2 * BBUF)            // 76160
#define SMEM_TOT (BNOFF + 1024)             // 77184

extern __shared__ char smem[];

// ---------------------------------------------------------------------------
// Fused conv(3x3,pad1) + BN + PACT via mma.sync implicit GEMM.
// CTA: image n, 4-row band (256 px tile, 224 used), 128 c_out half.
// 8 warps = 4(M) x 2(N), warp tile 64px x 64co (128 f32 acc regs).
// K loop: 8 ci-chunks x 9 taps x 2 k16 x {hi,lo}. Taps are pure address
// offsets into the staged X tile (no A rebuild). B double-buffered cp.async.
// ---------------------------------------------------------------------------
__global__ void __launch_bounds__(256, 1)
conv_mma_kernel(const float* __restrict__ x,
                const float* __restrict__ alpha,
                float* __restrict__ out) {
    const int tid   = threadIdx.x;
    const int lane  = tid & 31;
    const int wid   = tid >> 5;
    const int warpM = wid & 3;
    const int warpN = wid >> 2;
    const int band  = blockIdx.x;        // 0..13
    const int coH   = blockIdx.y;        // 0..1
    const int n     = blockIdx.z;        // 0..31
    const int y0    = band * 4;

    const uint32_t sb = (uint32_t)__cvta_generic_to_shared(smem);
    float* sScale = (float*)(smem + BNOFF);
    float* sBias  = (float*)(smem + BNOFF + 512);
    if (tid < 128) {
        sScale[tid] = g_scale[coH * 128 + tid];
        sBias[tid]  = g_bias[coH * 128 + tid];
    }

    // per-lane ldmatrix offsets
    uint32_t aoff[4];
    #pragma unroll
    for (int mf = 0; mf < 4; ++mf) {
        int pl = warpM * 64 + mf * 16 + (lane & 15);
        if (pl > 223) pl = 223;              // clamped rows; results discarded
        int pr = pl / 56, pc = pl - pr * 56;
        aoff[mf] = (uint32_t)((pr * CSTG + pc) * (CIPAD * 2)) + ((lane >> 4) << 4);
    }
    const uint32_t boffl =
        (uint32_t)(((((lane >> 4) & 1) * 8) + (lane & 7)) * (CIPAD * 2)) +
        (((lane >> 3) & 1) << 4);

    float acc[4][8][4] = {};

    // prologue: prefetch B(tap0, chunk0) into buf0
    for (int idx = tid; idx < 512; idx += 256) {
        int co = idx >> 2, seg = idx & 3;
        cp16(sb + BOFF + co * 80 + seg * 16,
             g_wqh + ((0 * COUT_ + coH * 128 + co) * CIN_ + 0 + seg * 8));
    }
    CP_COMMIT();

    int tt = 0;
    for (int c = 0; c < 8; ++c) {
        const int ci0 = c * 32;
        __syncthreads();                       // X buffers free
        // stage X chunk: fp32 global -> fp16 hi/lo smem [r][col][ci]
        for (int i = tid; i < RSTG * CSTG * 32; i += 256) {
            int cc  = i % CSTG;
            int rst = i / CSTG;
            int r   = rst % RSTG;
            int ci  = rst / RSTG;
            int iy  = y0 - 1 + r;
            int ix  = cc - 1;
            float v = 0.0f;
            if (iy >= 0 && iy < HW_ && ix >= 0 && ix < HW_)
                v = x[((n * CIN_ + ci0 + ci) * HW_ + iy) * HW_ + ix];
            __half h = __float2half_rn(v);
            __half l = __float2half_rn(v - __half2float(h));
            int o = (r * CSTG + cc) * CIPAD + ci;
            *(unsigned short*)(smem + o * 2)        = __half_as_ushort(h);
            *(unsigned short*)(smem + XARR + o * 2) = __half_as_ushort(l);
        }
        CP_WAIT0();
        __syncthreads();

        for (int t = 0; t < 9; ++t, ++tt) {
            const int buf = tt & 1;
            // prefetch next B tile
            if (tt + 1 < 72) {
                int t2 = (tt + 1) % 9, c2 = (tt + 1) / 9;
                for (int idx = tid; idx < 512; idx += 256) {
                    int co = idx >> 2, seg = idx & 3;
                    cp16(sb + BOFF + (buf ^ 1) * BBUF + co * 80 + seg * 16,
                         g_wqh + ((t2 * COUT_ + coH * 128 + co) * CIN_ +
                                  c2 * 32 + seg * 8));
                }
            }
            CP_COMMIT();

            const int ky = t / 3, kx = t - ky * 3;
            const uint32_t dtap = (uint32_t)((ky * CSTG + kx) * (CIPAD * 2));
            const uint32_t bbase = sb + BOFF + buf * BBUF + warpN * 64 * 80 + boffl;

            #pragma unroll
            for (int ks = 0; ks < 2; ++ks) {
                uint32_t bfr[4][4];
                #pragma unroll
                for (int nf = 0; nf < 4; ++nf)
                    LDSM4(bfr[nf], bbase + nf * 16 * 80 + ks * 32);
                #pragma unroll
                for (int half = 0; half < 2; ++half) {
                    uint32_t afr[4][4];
                    const uint32_t xb = sb + half * XARR + dtap + ks * 32;
                    #pragma unroll
                    for (int mf = 0; mf < 4; ++mf)
                        LDSM4(afr[mf], xb + aoff[mf]);
                    #pragma unroll
                    for (int mf = 0; mf < 4; ++mf)
                        #pragma unroll
                        for (int nf8 = 0; nf8 < 8; ++nf8)
                            MMA16816(acc[mf][nf8], afr[mf],
                                     bfr[nf8 >> 1][(nf8 & 1) * 2],
                                     bfr[nf8 >> 1][(nf8 & 1) * 2 + 1]);
                }
            }
            CP_WAIT0();
            __syncthreads();
        }
    }

    // ---- epilogue: per-warp smem transpose + BN + PACT, coalesced stores ----
    __syncthreads();
    const float aV   = __ldg(alpha);
    const float r15a = 15.0f / aV;
    const float a15  = aV / 15.0f;
    float* sbuf = (float*)(smem + wid * 4160);   // [16 co][65 px] per warp
    const int g  = lane >> 2;
    const int tq = lane & 3;

    for (int p = 0; p < 4; ++p) {
        __syncwarp();
        #pragma unroll
        for (int j = 0; j < 2; ++j) {
            const int nf8 = p * 2 + j;
            #pragma unroll
            for (int mf = 0; mf < 4; ++mf)
                #pragma unroll
                for (int r = 0; r < 4; ++r) {
                    int pxl = mf * 16 + g + (r >> 1) * 8;
                    int col = j * 8 + tq * 2 + (r & 1);
                    sbuf[col * 65 + pxl] = acc[mf][nf8][r];
                }
        }
        __syncwarp();
        #pragma unroll
        for (int cl = 0; cl < 16; ++cl) {
            const int coc = warpN * 64 + p * 16 + cl;
            const int co  = coH * 128 + coc;
            const float sc = sScale[coc], bi = sBias[coc];
            #pragma unroll
            for (int h2 = 0; h2 < 2; ++h2) {
                int pxl = lane + h2 * 32;
                int pxg = warpM * 64 + pxl;
                if (pxg < 224) {
                    float v = sbuf[cl * 65 + pxl] * sc + bi;
                    v = fminf(fmaxf(v, 0.0f), aV);
                    v = rintf(v * r15a) * a15;
                    out[(size_t)(n * COUT_ + co) * 3136 + y0 * 56 + pxg] = v;
                }
            }
        }
    }
}

// ---------------------------------------------------------------------------
// Launch
// ---------------------------------------------------------------------------
extern "C" void kernel_launch(void* const* d_in, const int* in_sizes, int n_in,
                              void* d_out, int out_size) {
    const float* x      = (const float*)d_in[0];
    const float* weight = (const float*)d_in[1];
    const float* gamma  = (const float*)d_in[2];
    const float* beta   = (const float*)d_in[3];
    const float* rmean  = (const float*)d_in[4];
    const float* rvar   = (const float*)d_in[5];
    const float* alpha  = (const float*)d_in[6];
    float* out = (float*)d_out;

    init_max_kernel<<<1, 1>>>();
    wmax_kernel<<<576, 256>>>(weight);
    wquant_h_kernel<<<(WN_ + 255) / 256, 256>>>(weight);
    bnprep_kernel<<<1, 256>>>(gamma, beta, rmean, rvar);

    cudaFuncSetAttribute(conv_mma_kernel,
                         cudaFuncAttributeMaxDynamicSharedMemorySize, SMEM_TOT);
    dim3 grid(14, 2, B_);
    conv_mma_kernel<<<grid, 256, SMEM_TOT>>>(x, alpha, out);
}